// round 5
// baseline (speedup 1.0000x reference)
#include <cuda_runtime.h>
#include <math.h>

#define T_LEN 2048
#define C_CH  64
#define NSC   5

// ---- sparse scale: 336 only (s=4) ----
#define PAD_SP  2689
#define XS_SP   (T_LEN + 2*PAD_SP)      // 7426
#define MAXTAPS 1088

// ---- dense scales (1, 27, 76, 167 -> s=0..3), window-sliding quads ----
#define PAD_DN  1344
#define CHUNK   1024
#define XS_DN   (CHUNK + 2*PAD_DN + 16) // 3728
#define WTOT    4416

// shared buffer: sparse uses xs[0,7426) + taps at 7428 (2176 floats)
//                dense  uses xs[0,3728) + W  at 3728 (4416 floats)
#define BUFSZ   9604
#define TAPOFS  7428

__constant__ int c_widths[5] = {1, 27, 76, 167, 336};
__constant__ int c_wofs[4]   = {0, 32, 480, 1712};
__constant__ int c_wcap[4]   = {32, 448, 1232, 2688};

__device__ float g_W[WTOT];     // dense weights, zero padded
__device__ int   g_rounds[4];
__device__ int   g_obase[4];
__device__ int2  g_taps[MAXTAPS];   // scale 336
__device__ int   g_cnt;

// ---------------------------------------------------------------------------
// Setup: 5 blocks, one per scale; each block recomputes psi + fp64 scan
// locally (no inter-block dependency). Index math (step, j = trunc(l/(s*step)))
// in exact fp64 with __d*_rn so fast-math can't fold it. Cumsum rounding ORDER
// only perturbs weights at ~1e-16; tap positions depend only on step (exact).
// ---------------------------------------------------------------------------
__global__ void k_setup() {
    __shared__ double ips[1024];
    __shared__ int    sc[1024];
    __shared__ int    sh_Lf;
    int tid = threadIdx.x;
    int s   = blockIdx.x;          // 0..4
    int scale = c_widths[s];

    double delta = 16.0 / 1023.0;
    double step  = __dsub_rn(__dadd_rn(__dmul_rn(1.0, delta), -8.0), -8.0);

    double t = (tid == 1023) ? 8.0 : __dadd_rn(__dmul_rn((double)tid, delta), -8.0);
    ips[tid] = __dmul_rn(exp(__dmul_rn(-0.5, __dmul_rn(t, t))), cos(__dmul_rn(5.0, t)));
    __syncthreads();
    for (int off = 1; off < 1024; off <<= 1) {   // Kogge-Stone inclusive scan
        double a = (tid >= off) ? ips[tid - off] : 0.0;
        __syncthreads();
        ips[tid] = __dadd_rn(ips[tid], a);
        __syncthreads();
    }

    double sstep = __dmul_rn((double)scale, step);
    int Lmax = scale * 16;

    if (tid == 0) {
        long long jm = (long long)(__ddiv_rn((double)Lmax, sstep));
        int Lf;
        if (jm < 1024) {
            Lf = Lmax + 1;
        } else {
            int lo = 0, hi = Lmax;
            while (lo < hi) {
                int mid = (lo + hi) >> 1;
                long long j = (long long)(__ddiv_rn((double)mid, sstep));
                if (j >= 1024) hi = mid; else lo = mid + 1;
            }
            Lf = lo;
        }
        sh_Lf = Lf;
    }
    __syncthreads();
    int Lf = sh_Lf;
    int locut  = (Lf - 2) / 2;
    int center = Lf - 1 - locut;
    float negs = (float)(-sqrt((double)scale));
    int total  = Lf + 1;               // h indices 0..Lf

    if (s < 4) {
        // -------- dense scatter into g_W --------
        int obase = -((center + 3) & ~3);
        if (tid == 0) {
            g_obase[s]  = obase;
            g_rounds[s] = ((Lf - center - obase) >> 2) + 1;
        }
        for (int i = tid; i < c_wcap[s]; i += 1024) g_W[c_wofs[s] + i] = 0.f;
        __syncthreads();
        for (int l = tid; l < total; l += 1024) {
            float fm1 = 0.f, fc = 0.f;
            if (l >= 1) {
                long long j = (long long)(__ddiv_rn((double)(l - 1), sstep));
                fm1 = (float)__dmul_rn(ips[j], step);
            }
            if (l < Lf) {
                long long j = (long long)(__ddiv_rn((double)l, sstep));
                fc = (float)__dmul_rn(ips[j], step);
            }
            float h = fm1 - fc;
            if (h != 0.f) {
                int k = l - center - obase;
                if (k >= 0 && k < c_wcap[s]) g_W[c_wofs[s] + k] = h * negs;
            }
        }
    } else {
        // -------- sparse compaction (chunked + parallel int scan) --------
        int chunk = (total + 1023) >> 10;     // 6 for scale 336
        int l0 = tid * chunk;
        int l1 = min(l0 + chunk, total);
        float lw[8]; int lof[8]; int lc = 0;
        for (int l = l0; l < l1; ++l) {
            float fm1 = 0.f, fc = 0.f;
            if (l >= 1) {
                long long j = (long long)(__ddiv_rn((double)(l - 1), sstep));
                fm1 = (float)__dmul_rn(ips[j], step);
            }
            if (l < Lf) {
                long long j = (long long)(__ddiv_rn((double)l, sstep));
                fc = (float)__dmul_rn(ips[j], step);
            }
            float h = fm1 - fc;
            if (h != 0.f && lc < 8) { lw[lc] = h * negs; lof[lc] = l - center; ++lc; }
        }
        sc[tid] = lc;
        __syncthreads();
        for (int off = 1; off < 1024; off <<= 1) {
            int a = (tid >= off) ? sc[tid - off] : 0;
            __syncthreads();
            sc[tid] += a;
            __syncthreads();
        }
        int base = sc[tid] - lc;
        if (tid == 1023) g_cnt = min(sc[1023], MAXTAPS);
        for (int i = 0; i < lc; ++i) {
            int p = base + i;
            if (p < MAXTAPS) g_taps[p] = make_int2(lof[i], __float_as_int(lw[i]));
        }
    }
}

// ---------------------------------------------------------------------------
// Main fused kernel. 3072 blocks: row = b/3, phase = b%3.
//   phase 0 (sparse, scale 336): full row, 8 accumulators at stride 256,
//     1 LDS.32 per MAC (crossbar-bound: taps have gaps 5-6, no reuse possible).
//   phase 1/2 (dense, scales 1,27,76,167; half = phase-1): 1024-output chunk,
//     4 consecutive outputs/thread; per round 1 LDS.128 x + broadcast w quad
//     + 16 FMA -> ~1 B/MAC (FMA-bound). Phase interleave mixes both kinds
//     on every SM so crossbar and FMA pipes overlap.
// ---------------------------------------------------------------------------
__global__ void __launch_bounds__(256) k_main(const float* __restrict__ x,
                                              float* __restrict__ out) {
    __shared__ __align__(16) float s_buf[BUFSZ];

    int b   = blockIdx.x;
    int tid = threadIdx.x;
    int row   = b / 3;
    int phase = b - 3 * row;
    int n = row >> 6, c = row & 63;
    const float* xrow = x + (size_t)n * T_LEN * C_CH + c;

    if (phase == 0) {
        // ================= sparse path (scale 336) =================
        float* xs = s_buf;
        int2*  tp = (int2*)(s_buf + TAPOFS);
        for (int i = tid; i < XS_SP; i += 256) {
            int g = i - PAD_SP;
            xs[i] = (g >= 0 && g < T_LEN) ? xrow[(size_t)g * C_CH] : 0.f;
        }
        int cnt = g_cnt;
        for (int i = tid; i < cnt; i += 256) tp[i] = g_taps[i];
        __syncthreads();

        float a0=0.f,a1=0.f,a2=0.f,a3=0.f,a4=0.f,a5=0.f,a6=0.f,a7=0.f;
        const float* base = xs + PAD_SP + tid;
        #pragma unroll 2
        for (int k = 0; k < cnt; ++k) {
            int2 t2 = tp[k];
            float w = __int_as_float(t2.y);
            const float* p = base + t2.x;
            a0 = fmaf(w, p[0],    a0);
            a1 = fmaf(w, p[256],  a1);
            a2 = fmaf(w, p[512],  a2);
            a3 = fmaf(w, p[768],  a3);
            a4 = fmaf(w, p[1024], a4);
            a5 = fmaf(w, p[1280], a5);
            a6 = fmaf(w, p[1536], a6);
            a7 = fmaf(w, p[1792], a7);
        }
        size_t ob = (((size_t)n * T_LEN + tid) * C_CH + c) * NSC + 4;
        const size_t st = (size_t)256 * C_CH * NSC;
        out[ob]        = a0;
        out[ob + st]   = a1;
        out[ob + 2*st] = a2;
        out[ob + 3*st] = a3;
        out[ob + 4*st] = a4;
        out[ob + 5*st] = a5;
        out[ob + 6*st] = a6;
        out[ob + 7*st] = a7;
    } else {
        // ================= dense window path (scales 1, 27, 76, 167) =====
        int tbase = (phase - 1) * CHUNK;
        float* xs = s_buf;
        float* sW = s_buf + XS_DN;
        for (int i = tid; i < XS_DN; i += 256) {
            int g = tbase + i - PAD_DN;
            xs[i] = (g >= 0 && g < T_LEN) ? xrow[(size_t)g * C_CH] : 0.f;
        }
        for (int i = tid; i < WTOT; i += 256) sW[i] = g_W[i];
        __syncthreads();

        const float4* xq = (const float4*)xs;
        int t0 = 4 * tid;
        #pragma unroll
        for (int s = 0; s < 4; ++s) {
            int wofs   = c_wofs[s];
            int obase  = g_obase[s];
            int rounds = g_rounds[s];
            int qb = (t0 + obase + PAD_DN) >> 2;   // whole quad index by construction

            float ax=0.f, ay=0.f, az=0.f, aw=0.f;
            float4 a = xq[qb];
            #pragma unroll 2
            for (int j = 0; j < rounds; ++j) {
                float4 w  = *(const float4*)(sW + wofs + 4*j);  // uniform broadcast
                float4 bq = xq[qb + j + 1];
                ax = fmaf(w.x,a.x, fmaf(w.y,a.y, fmaf(w.z,a.z,  fmaf(w.w,a.w,  ax))));
                ay = fmaf(w.x,a.y, fmaf(w.y,a.z, fmaf(w.z,a.w,  fmaf(w.w,bq.x, ay))));
                az = fmaf(w.x,a.z, fmaf(w.y,a.w, fmaf(w.z,bq.x, fmaf(w.w,bq.y, az))));
                aw = fmaf(w.x,a.w, fmaf(w.y,bq.x,fmaf(w.z,bq.y, fmaf(w.w,bq.z, aw))));
                a = bq;
            }
            size_t ob = (((size_t)n * T_LEN + tbase + t0) * C_CH + c) * NSC + s;
            const size_t st = (size_t)C_CH * NSC;  // 320
            out[ob]        = ax;
            out[ob + st]   = ay;
            out[ob + 2*st] = az;
            out[ob + 3*st] = aw;
        }
    }
}

extern "C" void kernel_launch(void* const* d_in, const int* in_sizes, int n_in,
                              void* d_out, int out_size) {
    const float* x = (const float*)d_in[0];
    float* out = (float*)d_out;
    (void)in_sizes; (void)n_in; (void)out_size;

    k_setup<<<5, 1024>>>();
    k_main<<<3072, 256>>>(x, out);
}

// round 8
// speedup vs baseline: 1.4325x; 1.4325x over previous
#include <cuda_runtime.h>
#include <cuda_fp16.h>
#include <math.h>
#include <stdint.h>

#define T_LEN   2048
#define PAD     2689
#define XS_LEN  7432
#define NFRAGS  1240          // 2 * sum(active ksteps) = 2*620
// scale order (desc): slot 0..4 = widths 336,167,76,27,1 ; out s = 4-slot

__constant__ int c_wdesc[5] = {336, 167, 76, 27, 1};
__constant__ int c_ja[5]    = {0, 83, 129, 153, 166};   // padded active kstep ranges
__constant__ int c_jb[5]    = {336, 252, 207, 182, 169};

// B fragments, pre-swizzled to mma.m16n8k16 B-register order.
// frag f (256B): lane*8 bytes = halves (k0,k0+1,k0+8,k0+9) for n=lane/4, k0=2*(lane%4).
__device__ __align__(16) __half g_B[NFRAGS * 128];

__device__ __forceinline__ int clampi(int v, int lo, int hi) {
    return v < lo ? lo : (v > hi ? hi : v);
}
// prefix of active-scale counts over ksteps (producer/consumer both use this)
__device__ __forceinline__ int Pj(int j) {
    return j + clampi(j - 83, 0, 170) + clampi(j - 129, 0, 79)
             + clampi(j - 153, 0, 30) + clampi(j - 166, 0, 4);
}

__device__ __forceinline__ uint32_t smem_u32(const void* p) {
    uint32_t a;
    asm("{ .reg .u64 t; cvta.to.shared.u64 t, %1; cvt.u32.u64 %0, t; }" : "=r"(a) : "l"(p));
    return a;
}
__device__ __forceinline__ uint32_t pack2(__half a, __half b) {
    __half2 h = __halves2half2(a, b);
    uint32_t u;
    memcpy(&u, &h, 4);
    return u;
}
#define LDMX4(r, addr) \
    asm volatile("ldmatrix.sync.aligned.m8n8.x4.shared.b16 {%0,%1,%2,%3}, [%4];" \
        : "=r"((r)[0]), "=r"((r)[1]), "=r"((r)[2]), "=r"((r)[3]) : "r"(addr))
#define MMA16816(d, a, b0, b1) \
    asm volatile("mma.sync.aligned.m16n8k16.row.col.f32.f16.f16.f32 " \
        "{%0,%1,%2,%3}, {%4,%5,%6,%7}, {%8,%9}, {%0,%1,%2,%3};" \
        : "+f"((d)[0]), "+f"((d)[1]), "+f"((d)[2]), "+f"((d)[3]) \
        : "r"((a)[0]), "r"((a)[1]), "r"((a)[2]), "r"((a)[3]), "r"(b0), "r"(b1))

// ---------------------------------------------------------------------------
// Setup: 5 blocks (one per scale). psi -> fp64 Kogge-Stone scan -> pre-swizzled
// B fragments. Index math (step, j = trunc(l/(s*step))) in exact fp64 with
// __d*_rn so fast-math can't fold it; Lf/center via the verified search.
// B[k][n] = -sqrt(s)*h[k - n - (2689-center)], split into wh + wl fp16 halves.
// ---------------------------------------------------------------------------
__global__ void k_setup() {
    __shared__ double ips[1024];
    __shared__ int sh_Lf;
    int tid = threadIdx.x;
    int sidx = blockIdx.x;
    int scale = c_wdesc[sidx];

    double delta = 16.0 / 1023.0;
    double step  = __dsub_rn(__dadd_rn(__dmul_rn(1.0, delta), -8.0), -8.0);

    double t = (tid == 1023) ? 8.0 : __dadd_rn(__dmul_rn((double)tid, delta), -8.0);
    ips[tid] = __dmul_rn(exp(__dmul_rn(-0.5, __dmul_rn(t, t))), cos(__dmul_rn(5.0, t)));
    __syncthreads();
    for (int off = 1; off < 1024; off <<= 1) {
        double a = (tid >= off) ? ips[tid - off] : 0.0;
        __syncthreads();
        ips[tid] = __dadd_rn(ips[tid], a);
        __syncthreads();
    }

    double sstep = __dmul_rn((double)scale, step);
    int Lmax = scale * 16;
    if (tid == 0) {
        long long jm = (long long)(__ddiv_rn((double)Lmax, sstep));
        int Lf;
        if (jm < 1024) {
            Lf = Lmax + 1;
        } else {
            int lo = 0, hi = Lmax;
            while (lo < hi) {
                int mid = (lo + hi) >> 1;
                long long j = (long long)(__ddiv_rn((double)mid, sstep));
                if (j >= 1024) hi = mid; else lo = mid + 1;
            }
            Lf = lo;
        }
        sh_Lf = Lf;
    }
    __syncthreads();
    int Lf = sh_Lf;
    int center = Lf - 1 - (Lf - 2) / 2;
    int Ds = PAD - center;
    float negs = -(float)sqrt((double)scale);

    int ja = c_ja[sidx], jb = c_jb[sidx];
    int nj = jb - ja + 1;
    for (int it = tid; it < nj * 32; it += 1024) {
        int j = ja + (it >> 5);
        int lane = it & 31;
        int k0 = 16 * j + 2 * (lane & 3);
        int nn = lane >> 2;
        float w[4];
        #pragma unroll
        for (int q = 0; q < 4; ++q) {
            int k = k0 + (q & 1) + (q >> 1) * 8;
            int m = k - nn - Ds;
            float v = 0.f;
            if (m >= 0 && m <= Lf) {
                float fm1 = 0.f, fc = 0.f;
                if (m >= 1) {
                    long long ji = (long long)__ddiv_rn((double)(m - 1), sstep);
                    fm1 = (float)__dmul_rn(ips[ji], step);
                }
                if (m < Lf) {
                    long long ji = (long long)__ddiv_rn((double)m, sstep);
                    fc = (float)__dmul_rn(ips[ji], step);
                }
                v = (fm1 - fc) * negs;
            }
            w[q] = v;
        }
        __half wh[4], wl[4];
        #pragma unroll
        for (int q = 0; q < 4; ++q) {
            wh[q] = __float2half(w[q]);
            wl[q] = __float2half(w[q] - __half2float(wh[q]));
        }
        size_t fb = (size_t)(Pj(j) + sidx) * 512;   // 2 frags of 256B
        uint2* dsth = (uint2*)((char*)g_B + fb + lane * 8);
        uint2* dstl = (uint2*)((char*)g_B + fb + 256 + lane * 8);
        *dsth = make_uint2(pack2(wh[0], wh[1]), pack2(wh[2], wh[3]));
        *dstl = make_uint2(pack2(wl[0], wl[1]), pack2(wl[2], wl[3]));
    }
}

// ---------------------------------------------------------------------------
// Consumer segment: NS active scales (nested ranges -> active set is always a
// prefix of slot order). Per kstep j: 4 ldmatrix.x4 A frags (Toeplitz aliasing,
// conflict-free), per scale 2 LDG.64 B frags + 8 HMMA (4 mtiles x 2 passes).
// ---------------------------------------------------------------------------
template<int NS>
__device__ __forceinline__ void run_range(int ja, int jb, uint32_t abase,
                                          uint32_t& boff, float (&D)[5][4][4],
                                          int lane) {
    const char* gb = (const char*)g_B;
    for (int j = ja; j <= jb; ++j) {
        uint32_t a[4][4];
        #pragma unroll
        for (int mt = 0; mt < 4; ++mt)
            LDMX4(a[mt], abase + mt * 256 + j * 32);
        #pragma unroll
        for (int si = 0; si < NS; ++si) {
            uint2 bh = *(const uint2*)(gb + boff + si * 512 + lane * 8);
            uint2 bl = *(const uint2*)(gb + boff + si * 512 + 256 + lane * 8);
            #pragma unroll
            for (int mt = 0; mt < 4; ++mt) {
                MMA16816(D[si][mt], a[mt], bh.x, bh.y);
                MMA16816(D[si][mt], a[mt], bl.x, bl.y);
            }
        }
        boff += NS * 512;
    }
}

__global__ void __launch_bounds__(128, 4) k_tc(const float* __restrict__ x,
                                               float* __restrict__ out) {
    __shared__ __align__(16) __half xs[XS_LEN];
    int tid = threadIdx.x;
    int wid = tid >> 5, lane = tid & 31;
    int row = blockIdx.x;
    int nb = row >> 6, c = row & 63;

    // prologue: padded row -> fp16
    const float* xrow = x + (size_t)nb * T_LEN * 64 + c;
    for (int i = tid; i < XS_LEN; i += 128) {
        int g = i - PAD;
        xs[i] = (g >= 0 && g < T_LEN) ? __float2half(__ldg(xrow + (size_t)g * 64)) : __half(0.f);
    }
    __syncthreads();

    int t0 = wid * 512;
    uint32_t abase = smem_u32(xs) + 2u * (uint32_t)(t0 + 8 * (lane & 15) + 8 * (lane >> 4));

    float D[5][4][4];
    #pragma unroll
    for (int si = 0; si < 5; ++si)
        #pragma unroll
        for (int mt = 0; mt < 4; ++mt)
            #pragma unroll
            for (int q = 0; q < 4; ++q) D[si][mt][q] = 0.f;

    uint32_t boff = 0;
    run_range<1>(0, 82, abase, boff, D, lane);
    run_range<2>(83, 128, abase, boff, D, lane);
    run_range<3>(129, 152, abase, boff, D, lane);
    run_range<4>(153, 165, abase, boff, D, lane);
    run_range<5>(166, 169, abase, boff, D, lane);
    run_range<4>(170, 182, abase, boff, D, lane);
    run_range<3>(183, 207, abase, boff, D, lane);
    run_range<2>(208, 252, abase, boff, D, lane);
    run_range<1>(253, 336, abase, boff, D, lane);

    // epilogue: D[m][n] -> out[t0 + 128*mt + 8m + n], scale slot si -> s = 4-si
    int mrow = lane >> 2;
    int ncol = (lane & 3) * 2;
    #pragma unroll
    for (int si = 0; si < 5; ++si) {
        int s_out = 4 - si;
        #pragma unroll
        for (int mt = 0; mt < 4; ++mt) {
            int t00 = t0 + mt * 128 + 8 * mrow + ncol;
            float* o = out + ((size_t)(nb * T_LEN + t00) * 64 + c) * 5 + s_out;
            o[0]        = D[si][mt][0];
            o[320]      = D[si][mt][1];   // t+1
            o[64 * 320] = D[si][mt][2];   // t+64 (m+8)
            o[65 * 320] = D[si][mt][3];
        }
    }
}

extern "C" void kernel_launch(void* const* d_in, const int* in_sizes, int n_in,
                              void* d_out, int out_size) {
    const float* x = (const float*)d_in[0];
    float* out = (float*)d_out;
    (void)in_sizes; (void)n_in; (void)out_size;

    k_setup<<<5, 1024>>>();
    k_tc<<<1024, 128>>>(x, out);
}

// round 9
// speedup vs baseline: 3.4358x; 2.3985x over previous
#include <cuda_runtime.h>
#include <cuda_fp16.h>
#include <math.h>
#include <stdint.h>

#define T_LEN   2048
#define PAD     2689
#define XS_LEN  7432
#define NFRAGS  620           // sum of active ksteps (single wh pass)
// scale order (desc): slot 0..4 = widths 336,167,76,27,1 ; out s = 4-slot

__constant__ int c_wdesc[5] = {336, 167, 76, 27, 1};
__constant__ int c_ja[5]    = {0, 83, 129, 153, 166};   // padded active kstep ranges
__constant__ int c_jb[5]    = {336, 252, 207, 182, 169};

// B fragments, pre-swizzled to mma.m16n8k16 B-register order.
// frag f (256B): lane*8 bytes = halves (k0,k0+1,k0+8,k0+9) for n=lane/4, k0=2*(lane%4).
__device__ __align__(16) __half g_B[NFRAGS * 128];

__device__ __forceinline__ int clampi(int v, int lo, int hi) {
    return v < lo ? lo : (v > hi ? hi : v);
}
// prefix of active-scale counts over ksteps (producer/consumer both use this)
__device__ __forceinline__ int Pj(int j) {
    return j + clampi(j - 83, 0, 170) + clampi(j - 129, 0, 79)
             + clampi(j - 153, 0, 30) + clampi(j - 166, 0, 4);
}

__device__ __forceinline__ uint32_t smem_u32(const void* p) {
    uint32_t a;
    asm("{ .reg .u64 t; cvta.to.shared.u64 t, %1; cvt.u32.u64 %0, t; }" : "=r"(a) : "l"(p));
    return a;
}
__device__ __forceinline__ uint32_t pack2(__half a, __half b) {
    __half2 h = __halves2half2(a, b);
    uint32_t u;
    memcpy(&u, &h, 4);
    return u;
}
#define LDMX4(r, addr) \
    asm volatile("ldmatrix.sync.aligned.m8n8.x4.shared.b16 {%0,%1,%2,%3}, [%4];" \
        : "=r"((r)[0]), "=r"((r)[1]), "=r"((r)[2]), "=r"((r)[3]) : "r"(addr))
#define MMA16816(d, a, b0, b1) \
    asm volatile("mma.sync.aligned.m16n8k16.row.col.f32.f16.f16.f32 " \
        "{%0,%1,%2,%3}, {%4,%5,%6,%7}, {%8,%9}, {%0,%1,%2,%3};" \
        : "+f"((d)[0]), "+f"((d)[1]), "+f"((d)[2]), "+f"((d)[3]) \
        : "r"((a)[0]), "r"((a)[1]), "r"((a)[2]), "r"((a)[3]), "r"(b0), "r"(b1))

// ---------------------------------------------------------------------------
// Setup: 5 blocks (one per scale). psi -> fp64 Kogge-Stone scan -> f[m] table
// in shared (ONE fp64 div per m) -> pre-swizzled B fragments from the float
// table. Index math (step, j = trunc(l/(s*step))) in exact fp64 with __d*_rn
// so fast-math can't fold it; Lf/center via the verified search.
// B[k][n] = -sqrt(s)*h[k - n - (2689-center)], h[m] = f[m-1]-f[m].
// ---------------------------------------------------------------------------
__global__ void k_setup() {
    __shared__ double ips[1024];
    __shared__ float  sh_f[5377];
    __shared__ int sh_Lf;
    int tid = threadIdx.x;
    int sidx = blockIdx.x;
    int scale = c_wdesc[sidx];

    double delta = 16.0 / 1023.0;
    double step  = __dsub_rn(__dadd_rn(__dmul_rn(1.0, delta), -8.0), -8.0);

    double t = (tid == 1023) ? 8.0 : __dadd_rn(__dmul_rn((double)tid, delta), -8.0);
    ips[tid] = __dmul_rn(exp(__dmul_rn(-0.5, __dmul_rn(t, t))), cos(__dmul_rn(5.0, t)));
    __syncthreads();
    for (int off = 1; off < 1024; off <<= 1) {
        double a = (tid >= off) ? ips[tid - off] : 0.0;
        __syncthreads();
        ips[tid] = __dadd_rn(ips[tid], a);
        __syncthreads();
    }

    double sstep = __dmul_rn((double)scale, step);
    int Lmax = scale * 16;
    if (tid == 0) {
        long long jm = (long long)(__ddiv_rn((double)Lmax, sstep));
        int Lf;
        if (jm < 1024) {
            Lf = Lmax + 1;
        } else {
            int lo = 0, hi = Lmax;
            while (lo < hi) {
                int mid = (lo + hi) >> 1;
                long long j = (long long)(__ddiv_rn((double)mid, sstep));
                if (j >= 1024) hi = mid; else lo = mid + 1;
            }
            Lf = lo;
        }
        sh_Lf = Lf;
    }
    __syncthreads();
    int Lf = sh_Lf;
    int center = Lf - 1 - (Lf - 2) / 2;
    int Ds = PAD - center;
    float negs = -(float)sqrt((double)scale);

    // f table: one fp64 div per m
    for (int m = tid; m < Lf; m += 1024) {
        long long ji = (long long)__ddiv_rn((double)m, sstep);
        sh_f[m] = (float)__dmul_rn(ips[ji], step);
    }
    __syncthreads();

    int ja = c_ja[sidx], jb = c_jb[sidx];
    int nj = jb - ja + 1;
    for (int it = tid; it < nj * 32; it += 1024) {
        int j = ja + (it >> 5);
        int lane = it & 31;
        int k0 = 16 * j + 2 * (lane & 3);
        int nn = lane >> 2;
        __half wh[4];
        #pragma unroll
        for (int q = 0; q < 4; ++q) {
            int k = k0 + (q & 1) + (q >> 1) * 8;
            int m = k - nn - Ds;
            float v = 0.f;
            if (m >= 0 && m <= Lf) {
                float fm1 = (m >= 1) ? sh_f[m - 1] : 0.f;
                float fc  = (m <  Lf) ? sh_f[m]     : 0.f;
                v = (fm1 - fc) * negs;
            }
            wh[q] = __float2half(v);
        }
        size_t fb = (size_t)(Pj(j) + sidx) * 256;   // one 256B frag
        uint2* dsth = (uint2*)((char*)g_B + fb + lane * 8);
        *dsth = make_uint2(pack2(wh[0], wh[1]), pack2(wh[2], wh[3]));
    }
}

// ---------------------------------------------------------------------------
// Consumer segment: NS active scales (nested ranges -> active set is always a
// prefix of slot order). Per kstep j: 4 ldmatrix.x4 A frags (Toeplitz aliasing,
// conflict-free), NS LDG.64 B frags, then a flat (si,mt) wave of 4*NS HMMAs —
// each accumulator touched once per j so the chains overlap on the tensor pipe.
// ---------------------------------------------------------------------------
template<int NS>
__device__ __forceinline__ void run_range(int ja, int jb, uint32_t abase,
                                          uint32_t& boff, float (&D)[5][4][4],
                                          int lane) {
    const char* gb = (const char*)g_B;
    #pragma unroll 2
    for (int j = ja; j <= jb; ++j) {
        uint32_t a[4][4];
        #pragma unroll
        for (int mt = 0; mt < 4; ++mt)
            LDMX4(a[mt], abase + mt * 256 + j * 32);
        uint2 b[NS];
        #pragma unroll
        for (int si = 0; si < NS; ++si)
            b[si] = *(const uint2*)(gb + boff + si * 256 + lane * 8);
        #pragma unroll
        for (int si = 0; si < NS; ++si)
            #pragma unroll
            for (int mt = 0; mt < 4; ++mt)
                MMA16816(D[si][mt], a[mt], b[si].x, b[si].y);
        boff += NS * 256;
    }
}

__global__ void __launch_bounds__(128, 4) k_tc(const float* __restrict__ x,
                                               float* __restrict__ out) {
    __shared__ __align__(16) __half xs[XS_LEN];
    int tid = threadIdx.x;
    int wid = tid >> 5, lane = tid & 31;
    int row = blockIdx.x;
    int nb = row >> 6, c = row & 63;

    // prologue: padded row -> fp16
    const float* xrow = x + (size_t)nb * T_LEN * 64 + c;
    for (int i = tid; i < XS_LEN; i += 128) {
        int g = i - PAD;
        xs[i] = (g >= 0 && g < T_LEN) ? __float2half(__ldg(xrow + (size_t)g * 64)) : __half(0.f);
    }
    __syncthreads();

    int t0 = wid * 512;
    uint32_t abase = smem_u32(xs) + 2u * (uint32_t)(t0 + 8 * (lane & 15) + 8 * (lane >> 4));

    float D[5][4][4];
    #pragma unroll
    for (int si = 0; si < 5; ++si)
        #pragma unroll
        for (int mt = 0; mt < 4; ++mt)
            #pragma unroll
            for (int q = 0; q < 4; ++q) D[si][mt][q] = 0.f;

    uint32_t boff = 0;
    run_range<1>(0, 82, abase, boff, D, lane);
    run_range<2>(83, 128, abase, boff, D, lane);
    run_range<3>(129, 152, abase, boff, D, lane);
    run_range<4>(153, 165, abase, boff, D, lane);
    run_range<5>(166, 169, abase, boff, D, lane);
    run_range<4>(170, 182, abase, boff, D, lane);
    run_range<3>(183, 207, abase, boff, D, lane);
    run_range<2>(208, 252, abase, boff, D, lane);
    run_range<1>(253, 336, abase, boff, D, lane);

    // epilogue: D[m][n] -> out[t0 + 128*mt + 8m + n], scale slot si -> s = 4-si
    int mrow = lane >> 2;
    int ncol = (lane & 3) * 2;
    #pragma unroll
    for (int si = 0; si < 5; ++si) {
        int s_out = 4 - si;
        #pragma unroll
        for (int mt = 0; mt < 4; ++mt) {
            int t00 = t0 + mt * 128 + 8 * mrow + ncol;
            float* o = out + ((size_t)(nb * T_LEN + t00) * 64 + c) * 5 + s_out;
            o[0]        = D[si][mt][0];
            o[320]      = D[si][mt][1];   // t+1
            o[64 * 320] = D[si][mt][2];   // t+64 (m+8)
            o[65 * 320] = D[si][mt][3];
        }
    }
}

extern "C" void kernel_launch(void* const* d_in, const int* in_sizes, int n_in,
                              void* d_out, int out_size) {
    const float* x = (const float*)d_in[0];
    float* out = (float*)d_out;
    (void)in_sizes; (void)n_in; (void)out_size;

    k_setup<<<5, 1024>>>();
    k_tc<<<1024, 128>>>(x, out);
}